// round 8
// baseline (speedup 1.0000x reference)
#include <cuda_runtime.h>
#include <cuda_fp16.h>
#include <mma.h>
#include <cuda_pipeline.h>
#include <cstdint>

using namespace nvcuda;

// Problem dims
#define M_TOT 8192          // 4*2048
#define N_TOT 14336
#define K_TOT 4096
#define NPACK (N_TOT * (K_TOT / 2))

// GEMM tiling (fp16 wmma 16x16x16, single K pass)
#define BM 128
#define BN 256
#define BK 64               // 64 fp16 per stage row (128B)
#define LDT 72              // smem row stride (halves): 64 + 8 pad (16B-aligned rows)
#define NT (K_TOT / BK)     // 64 k-iterations
#define STAGES 3
#define STAGE_HALVES ((BM + BN) * LDT)              // 27648 halves = 55296 B
#define SMEM_BYTES (STAGES * STAGE_HALVES * 2)      // 165888 B dynamic (1 CTA/SM)

// Rasterization: supertiles of GROUP_M m-tiles (fast) x all n-tiles
#define TILES_M (M_TOT / BM)      // 64
#define TILES_N (N_TOT / BN)      // 56
#define GROUP_M 16

// Scratch (static device globals: allocation-free per harness rules)
__device__ __align__(256) __half g_Ah[(size_t)M_TOT * K_TOT];   // 67 MB: x in fp16
__device__ __align__(256) __half g_Qh[(size_t)N_TOT * K_TOT];   // 117 MB: weights fp16
__device__ int g_swap_sb;   // 1 => sb0 is actually bias
__device__ int g_qw_i32;    // 1 => qweight stored as int32 (harness promoted int8)

// ---------------------------------------------------------------------------
// Probes: scale strictly positive (abs-max/7) vs bias (has negatives);
// qweight dtype: int32-promoted iff first 4096 words all in [-128,127].
// ---------------------------------------------------------------------------
__global__ void probe_kernel(const float* __restrict__ sb0,
                             const void* __restrict__ qw_raw) {
    __shared__ int s_neg, s_small;
    if (threadIdx.x == 0) { s_neg = 0; s_small = 1; }
    __syncthreads();
    int local_neg = 0;
    for (int i = threadIdx.x; i < N_TOT; i += blockDim.x)
        if (sb0[i] < 0.0f) local_neg = 1;
    if (local_neg) atomicOr(&s_neg, 1);
    const int* qw32 = (const int*)qw_raw;
    int local_big = 0;
    for (int i = threadIdx.x; i < 4096; i += blockDim.x) {
        int v = qw32[i];
        if (v < -128 || v > 127) local_big = 1;
    }
    if (local_big) atomicAnd(&s_small, 0);
    __syncthreads();
    if (threadIdx.x == 0) { g_swap_sb = s_neg; g_qw_i32 = s_small; }
}

// ---------------------------------------------------------------------------
// Prep 1: x fp32 -> fp16 (round-to-nearest).
// ---------------------------------------------------------------------------
__global__ void conv_x_kernel(const float* __restrict__ x) {
    int idx = blockIdx.x * blockDim.x + threadIdx.x;
    if (idx >= M_TOT * K_TOT) return;
    g_Ah[idx] = __float2half_rn(x[idx]);
}

// ---------------------------------------------------------------------------
// Prep 2: unpack 4-bit pairs -> fp16 integers in [-8,7] (exact in fp16).
// ---------------------------------------------------------------------------
__global__ void unpack_w_kernel(const void* __restrict__ qw_raw) {
    int idx = blockIdx.x * blockDim.x + threadIdx.x;
    if (idx >= NPACK) return;
    int v;
    if (g_qw_i32) v = ((const int*)qw_raw)[idx];
    else          v = (int)((const signed char*)qw_raw)[idx];
    int n = idx / (K_TOT / 2);
    int j = idx - n * (K_TOT / 2);
    int hi = v >> 4;
    int lo = ((v & 15) ^ 8) - 8;
    g_Qh[(size_t)n * K_TOT + 2 * j]     = __float2half_rn((float)hi);
    g_Qh[(size_t)n * K_TOT + 2 * j + 1] = __float2half_rn((float)lo);
}

// ---------------------------------------------------------------------------
// GEMM: out[m,n] = scale[n] * sum_k Ah[m,k]*Qh[n,k] + bias[n]
// 128x256 CTA tile, warp tile 64x64 (8 warps 2x4): LDSM:MMA = 8:16 per kk.
// BK=64, 3-stage cp.async, one __syncthreads per k-iter.
// ---------------------------------------------------------------------------
__global__ __launch_bounds__(256, 1) void gemm_f16_kernel(const float* __restrict__ sb0,
                                                          const float* __restrict__ sb1,
                                                          float* __restrict__ out) {
    extern __shared__ __align__(16) char dsm[];
    __half* smem_h = reinterpret_cast<__half*>(dsm);

    const int tid = threadIdx.x;

    // Supertile raster: bid -> (mt, nt); mt fastest within a GROUP_M band.
    const int bid = blockIdx.x;
    const int band = bid / (GROUP_M * TILES_N);
    const int within = bid - band * (GROUP_M * TILES_N);
    const int mt = band * GROUP_M + (within % GROUP_M);
    const int nt = within / GROUP_M;
    const int m0 = mt * BM;
    const int n0 = nt * BN;

    auto Abuf = [&](int s) { return smem_h + s * STAGE_HALVES; };
    auto Bbuf = [&](int s) { return smem_h + s * STAGE_HALVES + BM * LDT; };

    // Per stage: A = 128 rows x 8 chunks(16B), B = 256 rows x 8 chunks.
    // 256 threads: 4 A-chunks + 8 B-chunks each.
    auto issue = [&](int t) {
        const int s = t % STAGES;
        const int k0 = t * BK;
        __half* Ab = Abuf(s);
        __half* Bb = Bbuf(s);
        #pragma unroll
        for (int c = 0; c < 4; ++c) {
            int g = c * 256 + tid;
            int row = g >> 3, col = (g & 7) * 8;     // halves
            __pipeline_memcpy_async(Ab + row * LDT + col,
                                    g_Ah + (size_t)(m0 + row) * K_TOT + k0 + col, 16);
        }
        #pragma unroll
        for (int c = 0; c < 8; ++c) {
            int g = c * 256 + tid;
            int row = g >> 3, col = (g & 7) * 8;
            __pipeline_memcpy_async(Bb + row * LDT + col,
                                    g_Qh + (size_t)(n0 + row) * K_TOT + k0 + col, 16);
        }
    };

    const int warpId = tid >> 5;
    const int lane   = tid & 31;
    const int wm = (warpId & 1) * 64;   // 2 warps along M (128)
    const int wn = (warpId >> 1) * 64;  // 4 warps along N (256)

    wmma::fragment<wmma::matrix_a, 16, 16, 16, __half, wmma::row_major> fa[4];
    wmma::fragment<wmma::matrix_b, 16, 16, 16, __half, wmma::col_major> fb[4];
    wmma::fragment<wmma::accumulator, 16, 16, 16, float> acc[4][4];
    #pragma unroll
    for (int i = 0; i < 4; ++i)
        #pragma unroll
        for (int j = 0; j < 4; ++j)
            wmma::fill_fragment(acc[i][j], 0.0f);

    issue(0); __pipeline_commit();
    issue(1); __pipeline_commit();

    for (int t = 0; t < NT; ++t) {
        __pipeline_wait_prior((t + 1 < NT) ? 1 : 0);   // group t complete
        __syncthreads();                               // t visible; t-1 retired by all
        if (t + 2 < NT) {                              // refill buffer (t-1)%3
            issue(t + 2);
            __pipeline_commit();
        }
        const __half* As = Abuf(t % STAGES);
        const __half* Bs = Bbuf(t % STAGES);
        #pragma unroll
        for (int kk = 0; kk < BK; kk += 16) {
            #pragma unroll
            for (int i = 0; i < 4; ++i)
                wmma::load_matrix_sync(fa[i], As + (wm + i * 16) * LDT + kk, LDT);
            #pragma unroll
            for (int j = 0; j < 4; ++j)
                wmma::load_matrix_sync(fb[j], Bs + (wn + j * 16) * LDT + kk, LDT);
            #pragma unroll
            for (int i = 0; i < 4; ++i)
                #pragma unroll
                for (int j = 0; j < 4; ++j)
                    wmma::mma_sync(acc[i][j], fa[i], fb[j], acc[i][j]);
        }
    }

    // Epilogue: stage 16x16 tiles through per-warp smem, fuse scale/bias.
    __syncthreads();
    const float* scale = g_swap_sb ? sb1 : sb0;
    const float* bias  = g_swap_sb ? sb0 : sb1;
    float* cbuf = reinterpret_cast<float*>(dsm) + warpId * 256;   // 1KB/warp

    #pragma unroll
    for (int i = 0; i < 4; ++i) {
        #pragma unroll
        for (int j = 0; j < 4; ++j) {
            wmma::store_matrix_sync(cbuf, acc[i][j], 16, wmma::mem_row_major);
            __syncwarp();
            const int gm_base = m0 + wm + i * 16;
            const int gn_base = n0 + wn + j * 16;
            #pragma unroll
            for (int e = lane; e < 256; e += 32) {
                int r = e >> 4, c = e & 15;
                int gn = gn_base + c;
                out[(size_t)(gm_base + r) * N_TOT + gn] = cbuf[e] * scale[gn] + bias[gn];
            }
            __syncwarp();
        }
    }
}

// ---------------------------------------------------------------------------
extern "C" void kernel_launch(void* const* d_in, const int* in_sizes, int n_in,
                              void* d_out, int out_size) {
    (void)out_size;
    // Bind by element count: x 33554432 | qweight 29360128 | scale/bias 14336
    int ix = 0, iq = 1, isb0 = 2, isb1 = 3, nsb = 0;
    int sb_idx[2] = {2, 3};
    for (int i = 0; i < n_in && i < 8; ++i) {
        if (in_sizes[i] == M_TOT * K_TOT) ix = i;
        else if (in_sizes[i] == NPACK) iq = i;
        else if (in_sizes[i] == N_TOT && nsb < 2) sb_idx[nsb++] = i;
    }
    if (nsb == 2) { isb0 = sb_idx[0]; isb1 = sb_idx[1]; }

    const float* x   = (const float*)d_in[ix];
    const void*  qw  = d_in[iq];
    const float* sb0 = (const float*)d_in[isb0];
    const float* sb1 = (const float*)d_in[isb1];
    float*       out = (float*)d_out;

    probe_kernel<<<1, 1024>>>(sb0, qw);

    const int totalA = M_TOT * K_TOT;
    conv_x_kernel<<<(totalA + 255) / 256, 256>>>(x);
    unpack_w_kernel<<<(NPACK + 255) / 256, 256>>>(qw);

    cudaFuncSetAttribute(gemm_f16_kernel,
                         cudaFuncAttributeMaxDynamicSharedMemorySize, SMEM_BYTES);
    gemm_f16_kernel<<<TILES_M * TILES_N, 256, SMEM_BYTES>>>(sb0, sb1, out);
}

// round 9
// speedup vs baseline: 1.1390x; 1.1390x over previous
#include <cuda_runtime.h>
#include <cuda_fp16.h>
#include <mma.h>
#include <cuda_pipeline.h>
#include <cstdint>

using namespace nvcuda;

// Problem dims
#define M_TOT 8192          // 4*2048
#define N_TOT 14336
#define K_TOT 4096
#define NPACK (N_TOT * (K_TOT / 2))

// GEMM tiling (fp16 wmma 16x16x16, single K pass)
#define BM 128
#define BN 128
#define BK 64               // 64 fp16 per stage row (128B)
#define LDT 72              // smem row stride (halves): 64 + 8 pad (16B-aligned rows)
#define NT (K_TOT / BK)     // 64 k-iterations
#define STAGES 3
#define STAGE_HALVES ((BM + BN) * LDT)              // 18432 halves = 36864 B
#define SMEM_BYTES (STAGES * STAGE_HALVES * 2)      // 110592 B dynamic (2 CTAs/SM)

// Rasterization: supertiles of GROUP_M m-tiles (fast) x all n-tiles
#define TILES_M (M_TOT / BM)      // 64
#define TILES_N (N_TOT / BN)      // 112
#define GROUP_M 16

// Scratch (static device globals: allocation-free per harness rules)
__device__ __align__(256) __half g_Ah[(size_t)M_TOT * K_TOT];   // 67 MB: x in fp16
__device__ __align__(256) __half g_Qh[(size_t)N_TOT * K_TOT];   // 117 MB: weights fp16
__device__ int g_swap_sb;   // 1 => sb0 is actually bias
__device__ int g_qw_i32;    // 1 => qweight stored as int32 (harness promoted int8)

// ---------------------------------------------------------------------------
// Probes: scale strictly positive (abs-max/7) vs bias (has negatives);
// qweight dtype: int32-promoted iff first 4096 words all in [-128,127].
// ---------------------------------------------------------------------------
__global__ void probe_kernel(const float* __restrict__ sb0,
                             const void* __restrict__ qw_raw) {
    __shared__ int s_neg, s_small;
    if (threadIdx.x == 0) { s_neg = 0; s_small = 1; }
    __syncthreads();
    int local_neg = 0;
    for (int i = threadIdx.x; i < N_TOT; i += blockDim.x)
        if (sb0[i] < 0.0f) local_neg = 1;
    if (local_neg) atomicOr(&s_neg, 1);
    const int* qw32 = (const int*)qw_raw;
    int local_big = 0;
    for (int i = threadIdx.x; i < 4096; i += blockDim.x) {
        int v = qw32[i];
        if (v < -128 || v > 127) local_big = 1;
    }
    if (local_big) atomicAnd(&s_small, 0);
    __syncthreads();
    if (threadIdx.x == 0) { g_swap_sb = s_neg; g_qw_i32 = s_small; }
}

// ---------------------------------------------------------------------------
// Prep 1: x fp32 -> fp16 (round-to-nearest).
// ---------------------------------------------------------------------------
__global__ void conv_x_kernel(const float* __restrict__ x) {
    int idx = blockIdx.x * blockDim.x + threadIdx.x;
    if (idx >= M_TOT * K_TOT) return;
    g_Ah[idx] = __float2half_rn(x[idx]);
}

// ---------------------------------------------------------------------------
// Prep 2: unpack 4-bit pairs -> fp16 integers in [-8,7] (exact in fp16).
// ---------------------------------------------------------------------------
__global__ void unpack_w_kernel(const void* __restrict__ qw_raw) {
    int idx = blockIdx.x * blockDim.x + threadIdx.x;
    if (idx >= NPACK) return;
    int v;
    if (g_qw_i32) v = ((const int*)qw_raw)[idx];
    else          v = (int)((const signed char*)qw_raw)[idx];
    int n = idx / (K_TOT / 2);
    int j = idx - n * (K_TOT / 2);
    int hi = v >> 4;
    int lo = ((v & 15) ^ 8) - 8;
    g_Qh[(size_t)n * K_TOT + 2 * j]     = __float2half_rn((float)hi);
    g_Qh[(size_t)n * K_TOT + 2 * j + 1] = __float2half_rn((float)lo);
}

// ---------------------------------------------------------------------------
// GEMM: out[m,n] = scale[n] * sum_k Ah[m,k]*Qh[n,k] + bias[n]
// 128x128 tile, BK=64, 3-stage cp.async, one __syncthreads per k-iter.
// Mainloop reordered: fragment LDSMs issue FIRST each kk; next-stage cp.asyncs
// are spread 2-chunks-per-kk so the LSU never backs up ahead of the LDSMs.
// 8 warps (2x4), warp tile 64x32.
// ---------------------------------------------------------------------------
__global__ __launch_bounds__(256) void gemm_f16_kernel(const float* __restrict__ sb0,
                                                       const float* __restrict__ sb1,
                                                       float* __restrict__ out) {
    extern __shared__ __align__(16) char dsm[];
    __half* smem_h = reinterpret_cast<__half*>(dsm);

    const int tid = threadIdx.x;

    // Supertile raster: bid -> (mt, nt); mt fastest within a GROUP_M band.
    const int bid = blockIdx.x;
    const int band = bid / (GROUP_M * TILES_N);
    const int within = bid - band * (GROUP_M * TILES_N);
    const int mt = band * GROUP_M + (within % GROUP_M);
    const int nt = within / GROUP_M;
    const int m0 = mt * BM;
    const int n0 = nt * BN;

    auto Abuf = [&](int s) { return smem_h + s * STAGE_HALVES; };
    auto Bbuf = [&](int s) { return smem_h + s * STAGE_HALVES + BM * LDT; };

    // Per-thread load coords (fixed across iters): chunk q of A and B.
    const int ld_row = tid >> 3;             // g>>3 for g=tid (q folded below)
    // chunk index g = q*256 + tid -> row = g>>3, col = (g&7)*8
    auto issue_chunk = [&](int t, int q) {
        const int s = t % STAGES;
        const int k0 = t * BK;
        const int g = q * 256 + tid;
        const int row = g >> 3, col = (g & 7) * 8;   // halves
        __pipeline_memcpy_async(Abuf(s) + row * LDT + col,
                                g_Ah + (size_t)(m0 + row) * K_TOT + k0 + col, 16);
        __pipeline_memcpy_async(Bbuf(s) + row * LDT + col,
                                g_Qh + (size_t)(n0 + row) * K_TOT + k0 + col, 16);
    };
    auto issue_all = [&](int t) {
        #pragma unroll
        for (int q = 0; q < 4; ++q) issue_chunk(t, q);
    };
    (void)ld_row;

    const int warpId = tid >> 5;
    const int lane   = tid & 31;
    const int wm = (warpId & 1) * 64;   // 2 warps along M
    const int wn = (warpId >> 1) * 32;  // 4 warps along N

    wmma::fragment<wmma::matrix_a, 16, 16, 16, __half, wmma::row_major> fa[4];
    wmma::fragment<wmma::matrix_b, 16, 16, 16, __half, wmma::col_major> fb[2];
    wmma::fragment<wmma::accumulator, 16, 16, 16, float> acc[4][2];
    #pragma unroll
    for (int i = 0; i < 4; ++i)
        #pragma unroll
        for (int j = 0; j < 2; ++j)
            wmma::fill_fragment(acc[i][j], 0.0f);

    issue_all(0); __pipeline_commit();
    issue_all(1); __pipeline_commit();

    for (int t = 0; t < NT; ++t) {
        __pipeline_wait_prior((t + 1 < NT) ? 1 : 0);   // group t complete
        __syncthreads();                               // t visible; t-1 retired by all
        const __half* As = Abuf(t % STAGES);
        const __half* Bs = Bbuf(t % STAGES);
        const bool pre = (t + 2 < NT);
        #pragma unroll
        for (int kq = 0; kq < 4; ++kq) {
            const int kk = kq * 16;
            // Fragment loads FIRST: LDSMs reach the LSU before this kk's cp.asyncs.
            #pragma unroll
            for (int i = 0; i < 4; ++i)
                wmma::load_matrix_sync(fa[i], As + (wm + i * 16) * LDT + kk, LDT);
            #pragma unroll
            for (int j = 0; j < 2; ++j)
                wmma::load_matrix_sync(fb[j], Bs + (wn + j * 16) * LDT + kk, LDT);
            // Spread next-stage global->smem copies: 2 chunks per kk.
            if (pre) issue_chunk(t + 2, kq);
            #pragma unroll
            for (int i = 0; i < 4; ++i)
                #pragma unroll
                for (int j = 0; j < 2; ++j)
                    wmma::mma_sync(acc[i][j], fa[i], fb[j], acc[i][j]);
        }
        if (pre) __pipeline_commit();
    }

    // Epilogue: stage 16x16 tiles through per-warp smem, fuse scale/bias.
    __syncthreads();
    const float* scale = g_swap_sb ? sb1 : sb0;
    const float* bias  = g_swap_sb ? sb0 : sb1;
    float* cbuf = reinterpret_cast<float*>(dsm) + warpId * 256;   // 1KB/warp

    #pragma unroll
    for (int i = 0; i < 4; ++i) {
        #pragma unroll
        for (int j = 0; j < 2; ++j) {
            wmma::store_matrix_sync(cbuf, acc[i][j], 16, wmma::mem_row_major);
            __syncwarp();
            const int gm_base = m0 + wm + i * 16;
            const int gn_base = n0 + wn + j * 16;
            #pragma unroll
            for (int e = lane; e < 256; e += 32) {
                int r = e >> 4, c = e & 15;
                int gn = gn_base + c;
                out[(size_t)(gm_base + r) * N_TOT + gn] = cbuf[e] * scale[gn] + bias[gn];
            }
            __syncwarp();
        }
    }
}

// ---------------------------------------------------------------------------
extern "C" void kernel_launch(void* const* d_in, const int* in_sizes, int n_in,
                              void* d_out, int out_size) {
    (void)out_size;
    // Bind by element count: x 33554432 | qweight 29360128 | scale/bias 14336
    int ix = 0, iq = 1, isb0 = 2, isb1 = 3, nsb = 0;
    int sb_idx[2] = {2, 3};
    for (int i = 0; i < n_in && i < 8; ++i) {
        if (in_sizes[i] == M_TOT * K_TOT) ix = i;
        else if (in_sizes[i] == NPACK) iq = i;
        else if (in_sizes[i] == N_TOT && nsb < 2) sb_idx[nsb++] = i;
    }
    if (nsb == 2) { isb0 = sb_idx[0]; isb1 = sb_idx[1]; }

    const float* x   = (const float*)d_in[ix];
    const void*  qw  = d_in[iq];
    const float* sb0 = (const float*)d_in[isb0];
    const float* sb1 = (const float*)d_in[isb1];
    float*       out = (float*)d_out;

    probe_kernel<<<1, 1024>>>(sb0, qw);

    const int totalA = M_TOT * K_TOT;
    conv_x_kernel<<<(totalA + 255) / 256, 256>>>(x);
    unpack_w_kernel<<<(NPACK + 255) / 256, 256>>>(qw);

    cudaFuncSetAttribute(gemm_f16_kernel,
                         cudaFuncAttributeMaxDynamicSharedMemorySize, SMEM_BYTES);
    gemm_f16_kernel<<<TILES_M * TILES_N, 256, SMEM_BYTES>>>(sb0, sb1, out);
}

// round 10
// speedup vs baseline: 1.2549x; 1.1018x over previous
#include <cuda_runtime.h>
#include <cuda_fp16.h>
#include <mma.h>
#include <cuda_pipeline.h>
#include <cstdint>

using namespace nvcuda;

// Problem dims
#define M_TOT 8192          // 4*2048
#define N_TOT 14336
#define K_TOT 4096
#define NPACK (N_TOT * (K_TOT / 2))

// GEMM tiling (fp16 wmma 16x16x16, single K pass)
#define BM 128
#define BN 128
#define BK 64               // 64 fp16 per stage row (128B)
#define LDT 72              // smem row stride (halves): 64 + 8 pad (16B-aligned rows)
#define NT (K_TOT / BK)     // 64 k-iterations
#define STAGES 3
#define STAGE_HALVES ((BM + BN) * LDT)              // 18432 halves = 36864 B
#define SMEM_BYTES (STAGES * STAGE_HALVES * 2)      // 110592 B dynamic (2 CTAs/SM)

// Rasterization: supertiles of GROUP_M m-tiles (fast) x all n-tiles
#define TILES_M (M_TOT / BM)      // 64
#define TILES_N (N_TOT / BN)      // 112
#define GROUP_M 16

// Scratch (static device globals: allocation-free per harness rules)
__device__ __align__(256) __half g_Ah[(size_t)M_TOT * K_TOT];   // 67 MB: x in fp16
__device__ __align__(256) __half g_Qh[(size_t)N_TOT * K_TOT];   // 117 MB: weights fp16
__device__ int g_swap_sb;   // 1 => sb0 is actually bias
__device__ int g_qw_i32;    // 1 => qweight stored as int32 (harness promoted int8)

// ---------------------------------------------------------------------------
// Probes: scale strictly positive (abs-max/7) vs bias (has negatives);
// qweight dtype: int32-promoted iff first 4096 words all in [-128,127].
// ---------------------------------------------------------------------------
__global__ void probe_kernel(const float* __restrict__ sb0,
                             const void* __restrict__ qw_raw) {
    __shared__ int s_neg, s_small;
    if (threadIdx.x == 0) { s_neg = 0; s_small = 1; }
    __syncthreads();
    int local_neg = 0;
    for (int i = threadIdx.x; i < N_TOT; i += blockDim.x)
        if (sb0[i] < 0.0f) local_neg = 1;
    if (local_neg) atomicOr(&s_neg, 1);
    const int* qw32 = (const int*)qw_raw;
    int local_big = 0;
    for (int i = threadIdx.x; i < 4096; i += blockDim.x) {
        int v = qw32[i];
        if (v < -128 || v > 127) local_big = 1;
    }
    if (local_big) atomicAnd(&s_small, 0);
    __syncthreads();
    if (threadIdx.x == 0) { g_swap_sb = s_neg; g_qw_i32 = s_small; }
}

// ---------------------------------------------------------------------------
// Prep 1: x fp32 -> fp16, vectorized: 8 floats -> one 16B store.
// ---------------------------------------------------------------------------
__global__ void conv_x_kernel(const float* __restrict__ x) {
    int idx = blockIdx.x * blockDim.x + threadIdx.x;         // per 8 elements
    if (idx >= (M_TOT * K_TOT) / 8) return;
    const float4* xv = (const float4*)x;
    float4 a = xv[idx * 2];
    float4 b = xv[idx * 2 + 1];
    union { __half2 h2[4]; uint4 u; } o;
    o.h2[0] = __floats2half2_rn(a.x, a.y);
    o.h2[1] = __floats2half2_rn(a.z, a.w);
    o.h2[2] = __floats2half2_rn(b.x, b.y);
    o.h2[3] = __floats2half2_rn(b.z, b.w);
    ((uint4*)g_Ah)[idx] = o.u;
}

// ---------------------------------------------------------------------------
// Prep 2: unpack 4-bit pairs -> fp16 in [-8,7], vectorized: 4 packed bytes
// (one row-contiguous group) -> 8 halves -> one 16B store. Handles both the
// native-int8 and the int32-promoted storage layouts.
// ---------------------------------------------------------------------------
__device__ __forceinline__ __half2 dec_pair(int v) {
    int hi = v >> 4;                   // arithmetic shift: even column
    int lo = ((v & 15) ^ 8) - 8;       // sign-extended low nibble: odd column
    return __floats2half2_rn((float)hi, (float)lo);
}
__global__ void unpack_w_kernel(const void* __restrict__ qw_raw) {
    int idx = blockIdx.x * blockDim.x + threadIdx.x;         // per 4 packed bytes
    if (idx >= NPACK / 4) return;
    int b0, b1, b2, b3;
    if (g_qw_i32) {
        int4 w = ((const int4*)qw_raw)[idx];
        b0 = w.x; b1 = w.y; b2 = w.z; b3 = w.w;
    } else {
        int w = ((const int*)qw_raw)[idx];
        b0 = (int)(signed char)(w);
        b1 = (int)(signed char)(w >> 8);
        b2 = (int)(signed char)(w >> 16);
        b3 = (int)(signed char)(w >> 24);
    }
    union { __half2 h2[4]; uint4 u; } o;
    o.h2[0] = dec_pair(b0);
    o.h2[1] = dec_pair(b1);
    o.h2[2] = dec_pair(b2);
    o.h2[3] = dec_pair(b3);
    ((uint4*)g_Qh)[idx] = o.u;
}

// ---------------------------------------------------------------------------
// GEMM: out[m,n] = scale[n] * sum_k Ah[m,k]*Qh[n,k] + bias[n]
// 128x128 tile, BK=64, 3-stage cp.async, one __syncthreads per k-iter.
// LDSMs first each kk; next-stage cp.asyncs spread 1-chunk-per-kk; all
// cp.async addresses are hoisted pointers (base + compile-time offset).
// 8 warps (2x4), warp tile 64x32.
// ---------------------------------------------------------------------------
__global__ __launch_bounds__(256) void gemm_f16_kernel(const float* __restrict__ sb0,
                                                       const float* __restrict__ sb1,
                                                       float* __restrict__ out) {
    extern __shared__ __align__(16) char dsm[];
    __half* smem_h = reinterpret_cast<__half*>(dsm);

    const int tid = threadIdx.x;

    // Supertile raster: bid -> (mt, nt); mt fastest within a GROUP_M band.
    const int bid = blockIdx.x;
    const int band = bid / (GROUP_M * TILES_N);
    const int within = bid - band * (GROUP_M * TILES_N);
    const int mt = band * GROUP_M + (within % GROUP_M);
    const int nt = within / GROUP_M;
    const int m0 = mt * BM;
    const int n0 = nt * BN;

    // Hoisted per-thread load geometry: chunk q covers rows q*32 + (tid>>3),
    // column (tid&7)*8 halves. Global bases advance by BK per k-iter.
    const int lrow = tid >> 3;
    const int lcol = (tid & 7) * 8;
    const __half* gA = g_Ah + (size_t)(m0 + lrow) * K_TOT + lcol;
    const __half* gB = g_Qh + (size_t)(n0 + lrow) * K_TOT + lcol;
    __half* sAd[STAGES];
    __half* sBd[STAGES];
    #pragma unroll
    for (int s = 0; s < STAGES; ++s) {
        sAd[s] = smem_h + s * STAGE_HALVES + lrow * LDT + lcol;
        sBd[s] = smem_h + s * STAGE_HALVES + BM * LDT + lrow * LDT + lcol;
    }

    auto issue_q = [&](int s, const __half* A, const __half* B, int q) {
        __pipeline_memcpy_async(sAd[s] + q * (32 * LDT), A + q * (32 * K_TOT), 16);
        __pipeline_memcpy_async(sBd[s] + q * (32 * LDT), B + q * (32 * K_TOT), 16);
    };

    const int warpId = tid >> 5;
    const int lane   = tid & 31;
    const int wm = (warpId & 1) * 64;   // 2 warps along M
    const int wn = (warpId >> 1) * 32;  // 4 warps along N

    wmma::fragment<wmma::matrix_a, 16, 16, 16, __half, wmma::row_major> fa[4];
    wmma::fragment<wmma::matrix_b, 16, 16, 16, __half, wmma::col_major> fb[2];
    wmma::fragment<wmma::accumulator, 16, 16, 16, float> acc[4][2];
    #pragma unroll
    for (int i = 0; i < 4; ++i)
        #pragma unroll
        for (int j = 0; j < 2; ++j)
            wmma::fill_fragment(acc[i][j], 0.0f);

    // Prologue: stages 0 and 1
    #pragma unroll
    for (int q = 0; q < 4; ++q) issue_q(0, gA, gB, q);
    __pipeline_commit();
    #pragma unroll
    for (int q = 0; q < 4; ++q) issue_q(1, gA + BK, gB + BK, q);
    __pipeline_commit();

    const __half* pfA = gA + 2 * BK;    // prefetch pointers (stage t+2)
    const __half* pfB = gB + 2 * BK;
    int sc = 0;                         // consume stage
    int sp = 2;                         // prefetch stage

    for (int t = 0; t < NT; ++t) {
        __pipeline_wait_prior((t + 1 < NT) ? 1 : 0);   // group t complete
        __syncthreads();                               // t visible; t-1 retired by all
        const __half* As = smem_h + sc * STAGE_HALVES;
        const __half* Bs = As + BM * LDT;
        const bool pre = (t + 2 < NT);
        #pragma unroll
        for (int kq = 0; kq < 4; ++kq) {
            const int kk = kq * 16;
            #pragma unroll
            for (int i = 0; i < 4; ++i)
                wmma::load_matrix_sync(fa[i], As + (wm + i * 16) * LDT + kk, LDT);
            #pragma unroll
            for (int j = 0; j < 2; ++j)
                wmma::load_matrix_sync(fb[j], Bs + (wn + j * 16) * LDT + kk, LDT);
            if (pre) issue_q(sp, pfA, pfB, kq);
            #pragma unroll
            for (int i = 0; i < 4; ++i)
                #pragma unroll
                for (int j = 0; j < 2; ++j)
                    wmma::mma_sync(acc[i][j], fa[i], fb[j], acc[i][j]);
        }
        if (pre) __pipeline_commit();
        pfA += BK; pfB += BK;
        sc = (sc == STAGES - 1) ? 0 : sc + 1;
        sp = (sp == STAGES - 1) ? 0 : sp + 1;
    }

    // Epilogue: stage 16x16 tiles through per-warp smem, fuse scale/bias.
    __syncthreads();
    const float* scale = g_swap_sb ? sb1 : sb0;
    const float* bias  = g_swap_sb ? sb0 : sb1;
    float* cbuf = reinterpret_cast<float*>(dsm) + warpId * 256;   // 1KB/warp

    #pragma unroll
    for (int i = 0; i < 4; ++i) {
        #pragma unroll
        for (int j = 0; j < 2; ++j) {
            wmma::store_matrix_sync(cbuf, acc[i][j], 16, wmma::mem_row_major);
            __syncwarp();
            const int gm_base = m0 + wm + i * 16;
            const int gn_base = n0 + wn + j * 16;
            #pragma unroll
            for (int e = lane; e < 256; e += 32) {
                int r = e >> 4, c = e & 15;
                int gn = gn_base + c;
                out[(size_t)(gm_base + r) * N_TOT + gn] = cbuf[e] * scale[gn] + bias[gn];
            }
            __syncwarp();
        }
    }
}

// ---------------------------------------------------------------------------
extern "C" void kernel_launch(void* const* d_in, const int* in_sizes, int n_in,
                              void* d_out, int out_size) {
    (void)out_size;
    // Bind by element count: x 33554432 | qweight 29360128 | scale/bias 14336
    int ix = 0, iq = 1, isb0 = 2, isb1 = 3, nsb = 0;
    int sb_idx[2] = {2, 3};
    for (int i = 0; i < n_in && i < 8; ++i) {
        if (in_sizes[i] == M_TOT * K_TOT) ix = i;
        else if (in_sizes[i] == NPACK) iq = i;
        else if (in_sizes[i] == N_TOT && nsb < 2) sb_idx[nsb++] = i;
    }
    if (nsb == 2) { isb0 = sb_idx[0]; isb1 = sb_idx[1]; }

    const float* x   = (const float*)d_in[ix];
    const void*  qw  = d_in[iq];
    const float* sb0 = (const float*)d_in[isb0];
    const float* sb1 = (const float*)d_in[isb1];
    float*       out = (float*)d_out;

    probe_kernel<<<1, 1024>>>(sb0, qw);

    const int vecA = (M_TOT * K_TOT) / 8;
    conv_x_kernel<<<(vecA + 255) / 256, 256>>>(x);
    const int vecW = NPACK / 4;
    unpack_w_kernel<<<(vecW + 255) / 256, 256>>>(qw);

    cudaFuncSetAttribute(gemm_f16_kernel,
                         cudaFuncAttributeMaxDynamicSharedMemorySize, SMEM_BYTES);
    gemm_f16_kernel<<<TILES_M * TILES_N, 256, SMEM_BYTES>>>(sb0, sb1, out);
}

// round 11
// speedup vs baseline: 1.2902x; 1.0281x over previous
#include <cuda_runtime.h>
#include <cuda_fp16.h>
#include <mma.h>
#include <cuda_pipeline.h>
#include <cstdint>

using namespace nvcuda;

// Problem dims
#define M_TOT 8192          // 4*2048
#define N_TOT 14336
#define K_TOT 4096
#define NPACK (N_TOT * (K_TOT / 2))

// GEMM tiling (fp16 wmma 16x16x16, single K pass)
#define BM 128
#define BN 128
#define BK 64               // 64 fp16 per stage row (128B)
#define LDT 72              // smem row stride (halves): 64 + 8 pad (16B-aligned rows)
#define NT (K_TOT / BK)     // 64 k-iterations
#define STAGES 3
#define STAGE_HALVES ((BM + BN) * LDT)              // 18432 halves = 36864 B
#define SMEM_BYTES (STAGES * STAGE_HALVES * 2)      // 110592 B dynamic (2 CTAs/SM)
#define NTHREADS 128        // 4 warps, warp tile 64x64 (2x2)

// Rasterization: supertiles of GROUP_M m-tiles (fast) x all n-tiles
#define TILES_M (M_TOT / BM)      // 64
#define TILES_N (N_TOT / BN)      // 112
#define GROUP_M 16

// Scratch (static device globals: allocation-free per harness rules)
__device__ __align__(256) __half g_Ah[(size_t)M_TOT * K_TOT];   // 67 MB: x in fp16
__device__ __align__(256) __half g_Qh[(size_t)N_TOT * K_TOT];   // 117 MB: weights fp16
__device__ int g_swap_sb;   // 1 => sb0 is actually bias
__device__ int g_qw_i32;    // 1 => qweight stored as int32 (harness promoted int8)

// ---------------------------------------------------------------------------
// Probes: scale strictly positive (abs-max/7) vs bias (has negatives);
// qweight dtype: int32-promoted iff first 4096 words all in [-128,127].
// ---------------------------------------------------------------------------
__global__ void probe_kernel(const float* __restrict__ sb0,
                             const void* __restrict__ qw_raw) {
    __shared__ int s_neg, s_small;
    if (threadIdx.x == 0) { s_neg = 0; s_small = 1; }
    __syncthreads();
    int local_neg = 0;
    for (int i = threadIdx.x; i < N_TOT; i += blockDim.x)
        if (sb0[i] < 0.0f) local_neg = 1;
    if (local_neg) atomicOr(&s_neg, 1);
    const int* qw32 = (const int*)qw_raw;
    int local_big = 0;
    for (int i = threadIdx.x; i < 4096; i += blockDim.x) {
        int v = qw32[i];
        if (v < -128 || v > 127) local_big = 1;
    }
    if (local_big) atomicAnd(&s_small, 0);
    __syncthreads();
    if (threadIdx.x == 0) { g_swap_sb = s_neg; g_qw_i32 = s_small; }
}

// ---------------------------------------------------------------------------
// Prep 1: x fp32 -> fp16, vectorized: 8 floats -> one 16B store.
// ---------------------------------------------------------------------------
__global__ void conv_x_kernel(const float* __restrict__ x) {
    int idx = blockIdx.x * blockDim.x + threadIdx.x;         // per 8 elements
    if (idx >= (M_TOT * K_TOT) / 8) return;
    const float4* xv = (const float4*)x;
    float4 a = xv[idx * 2];
    float4 b = xv[idx * 2 + 1];
    union { __half2 h2[4]; uint4 u; } o;
    o.h2[0] = __floats2half2_rn(a.x, a.y);
    o.h2[1] = __floats2half2_rn(a.z, a.w);
    o.h2[2] = __floats2half2_rn(b.x, b.y);
    o.h2[3] = __floats2half2_rn(b.z, b.w);
    ((uint4*)g_Ah)[idx] = o.u;
}

// ---------------------------------------------------------------------------
// Prep 2: unpack 4-bit pairs -> fp16 in [-8,7], vectorized.
// ---------------------------------------------------------------------------
__device__ __forceinline__ __half2 dec_pair(int v) {
    int hi = v >> 4;                   // arithmetic shift: even column
    int lo = ((v & 15) ^ 8) - 8;       // sign-extended low nibble: odd column
    return __floats2half2_rn((float)hi, (float)lo);
}
__global__ void unpack_w_kernel(const void* __restrict__ qw_raw) {
    int idx = blockIdx.x * blockDim.x + threadIdx.x;         // per 4 packed bytes
    if (idx >= NPACK / 4) return;
    int b0, b1, b2, b3;
    if (g_qw_i32) {
        int4 w = ((const int4*)qw_raw)[idx];
        b0 = w.x; b1 = w.y; b2 = w.z; b3 = w.w;
    } else {
        int w = ((const int*)qw_raw)[idx];
        b0 = (int)(signed char)(w);
        b1 = (int)(signed char)(w >> 8);
        b2 = (int)(signed char)(w >> 16);
        b3 = (int)(signed char)(w >> 24);
    }
    union { __half2 h2[4]; uint4 u; } o;
    o.h2[0] = dec_pair(b0);
    o.h2[1] = dec_pair(b1);
    o.h2[2] = dec_pair(b2);
    o.h2[3] = dec_pair(b3);
    ((uint4*)g_Qh)[idx] = o.u;
}

// ---------------------------------------------------------------------------
// GEMM: out[m,n] = scale[n] * sum_k Ah[m,k]*Qh[n,k] + bias[n]
// 128x128 CTA tile, 4 warps, warp tile 64x64: LDSM:MMA = 8:32 per kk.
// BK=64, 3-stage cp.async (2 CTAs/SM), LDSMs first, loads spread across kks,
// hoisted pointers.
// ---------------------------------------------------------------------------
__global__ __launch_bounds__(NTHREADS) void gemm_f16_kernel(const float* __restrict__ sb0,
                                                            const float* __restrict__ sb1,
                                                            float* __restrict__ out) {
    extern __shared__ __align__(16) char dsm[];
    __half* smem_h = reinterpret_cast<__half*>(dsm);

    const int tid = threadIdx.x;

    // Supertile raster: bid -> (mt, nt); mt fastest within a GROUP_M band.
    const int bid = blockIdx.x;
    const int band = bid / (GROUP_M * TILES_N);
    const int within = bid - band * (GROUP_M * TILES_N);
    const int mt = band * GROUP_M + (within % GROUP_M);
    const int nt = within / GROUP_M;
    const int m0 = mt * BM;
    const int n0 = nt * BN;

    // Hoisted per-thread load geometry: 128 threads cover 16 rows x 8 cols of
    // 16B chunks; chunk q adds 16 rows. 8 q's each for A and B per stage.
    const int lrow = tid >> 3;              // [0,16)
    const int lcol = (tid & 7) * 8;         // halves
    const __half* gA = g_Ah + (size_t)(m0 + lrow) * K_TOT + lcol;
    const __half* gB = g_Qh + (size_t)(n0 + lrow) * K_TOT + lcol;
    __half* sAd[STAGES];
    __half* sBd[STAGES];
    #pragma unroll
    for (int s = 0; s < STAGES; ++s) {
        sAd[s] = smem_h + s * STAGE_HALVES + lrow * LDT + lcol;
        sBd[s] = smem_h + s * STAGE_HALVES + BM * LDT + lrow * LDT + lcol;
    }

    // One A-chunk + one B-chunk at offset q*16 rows.
    auto issue_q = [&](int s, const __half* A, const __half* B, int q) {
        __pipeline_memcpy_async(sAd[s] + q * (16 * LDT), A + q * (size_t)(16 * K_TOT), 16);
        __pipeline_memcpy_async(sBd[s] + q * (16 * LDT), B + q * (size_t)(16 * K_TOT), 16);
    };
    auto issue_all = [&](int s, const __half* A, const __half* B) {
        #pragma unroll
        for (int q = 0; q < 8; ++q) issue_q(s, A, B, q);
    };

    const int warpId = tid >> 5;
    const int lane   = tid & 31;
    const int wm = (warpId & 1) * 64;   // 2 warps along M
    const int wn = (warpId >> 1) * 64;  // 2 warps along N

    wmma::fragment<wmma::matrix_a, 16, 16, 16, __half, wmma::row_major> fa[4];
    wmma::fragment<wmma::matrix_b, 16, 16, 16, __half, wmma::col_major> fb[4];
    wmma::fragment<wmma::accumulator, 16, 16, 16, float> acc[4][4];
    #pragma unroll
    for (int i = 0; i < 4; ++i)
        #pragma unroll
        for (int j = 0; j < 4; ++j)
            wmma::fill_fragment(acc[i][j], 0.0f);

    // Prologue: stages 0 and 1
    issue_all(0, gA, gB);        __pipeline_commit();
    issue_all(1, gA + BK, gB + BK); __pipeline_commit();

    const __half* pfA = gA + 2 * BK;    // prefetch pointers (stage t+2)
    const __half* pfB = gB + 2 * BK;
    int sc = 0;                         // consume stage
    int sp = 2;                         // prefetch stage

    for (int t = 0; t < NT; ++t) {
        __pipeline_wait_prior((t + 1 < NT) ? 1 : 0);   // group t complete
        __syncthreads();                               // t visible; t-1 retired by all
        const __half* As = smem_h + sc * STAGE_HALVES;
        const __half* Bs = As + BM * LDT;
        const bool pre = (t + 2 < NT);
        #pragma unroll
        for (int kq = 0; kq < 4; ++kq) {
            const int kk = kq * 16;
            // Fragment loads FIRST (LSU sees LDSMs before this kk's cp.asyncs).
            #pragma unroll
            for (int i = 0; i < 4; ++i)
                wmma::load_matrix_sync(fa[i], As + (wm + i * 16) * LDT + kk, LDT);
            #pragma unroll
            for (int j = 0; j < 4; ++j)
                wmma::load_matrix_sync(fb[j], Bs + (wn + j * 16) * LDT + kk, LDT);
            // Spread next-stage copies: 2 (A,B) chunk pairs per kk.
            if (pre) {
                issue_q(sp, pfA, pfB, kq * 2);
                issue_q(sp, pfA, pfB, kq * 2 + 1);
            }
            #pragma unroll
            for (int i = 0; i < 4; ++i)
                #pragma unroll
                for (int j = 0; j < 4; ++j)
                    wmma::mma_sync(acc[i][j], fa[i], fb[j], acc[i][j]);
        }
        if (pre) __pipeline_commit();
        pfA += BK; pfB += BK;
        sc = (sc == STAGES - 1) ? 0 : sc + 1;
        sp = (sp == STAGES - 1) ? 0 : sp + 1;
    }

    // Epilogue: stage 16x16 tiles through per-warp smem, fuse scale/bias.
    __syncthreads();
    const float* scale = g_swap_sb ? sb1 : sb0;
    const float* bias  = g_swap_sb ? sb0 : sb1;
    float* cbuf = reinterpret_cast<float*>(dsm) + warpId * 256;   // 1KB/warp

    #pragma unroll
    for (int i = 0; i < 4; ++i) {
        #pragma unroll
        for (int j = 0; j < 4; ++j) {
            wmma::store_matrix_sync(cbuf, acc[i][j], 16, wmma::mem_row_major);
            __syncwarp();
            const int gm_base = m0 + wm + i * 16;
            const int gn_base = n0 + wn + j * 16;
            #pragma unroll
            for (int e = lane; e < 256; e += 32) {
                int r = e >> 4, c = e & 15;
                int gn = gn_base + c;
                out[(size_t)(gm_base + r) * N_TOT + gn] = cbuf[e] * scale[gn] + bias[gn];
            }
            __syncwarp();
        }
    }
}

// ---------------------------------------------------------------------------
extern "C" void kernel_launch(void* const* d_in, const int* in_sizes, int n_in,
                              void* d_out, int out_size) {
    (void)out_size;
    // Bind by element count: x 33554432 | qweight 29360128 | scale/bias 14336
    int ix = 0, iq = 1, isb0 = 2, isb1 = 3, nsb = 0;
    int sb_idx[2] = {2, 3};
    for (int i = 0; i < n_in && i < 8; ++i) {
        if (in_sizes[i] == M_TOT * K_TOT) ix = i;
        else if (in_sizes[i] == NPACK) iq = i;
        else if (in_sizes[i] == N_TOT && nsb < 2) sb_idx[nsb++] = i;
    }
    if (nsb == 2) { isb0 = sb_idx[0]; isb1 = sb_idx[1]; }

    const float* x   = (const float*)d_in[ix];
    const void*  qw  = d_in[iq];
    const float* sb0 = (const float*)d_in[isb0];
    const float* sb1 = (const float*)d_in[isb1];
    float*       out = (float*)d_out;

    probe_kernel<<<1, 1024>>>(sb0, qw);

    const int vecA = (M_TOT * K_TOT) / 8;
    conv_x_kernel<<<(vecA + 255) / 256, 256>>>(x);
    const int vecW = NPACK / 4;
    unpack_w_kernel<<<(vecW + 255) / 256, 256>>>(qw);

    cudaFuncSetAttribute(gemm_f16_kernel,
                         cudaFuncAttributeMaxDynamicSharedMemorySize, SMEM_BYTES);
    gemm_f16_kernel<<<TILES_M * TILES_N, NTHREADS, SMEM_BYTES>>>(sb0, sb1, out);
}